// round 5
// baseline (speedup 1.0000x reference)
#include <cuda_runtime.h>
#include <stdint.h>

// ============================================================================
// EnhancedAntiOverfittingAugmentation — round 5: two streaming kernels,
// d_out as intermediate (harness buffer, fully overwritten, deterministic).
//  A: input -> SMEM (RG interleaved + B plane, 2px zero border) -> bilinear
//     affine gather + hflip -> warped planar image to d_out. 54KB smem,
//     256 thr, 4 CTAs/SM.
//  B: warped sample from d_out -> 1px-zero-padded SMEM, in-CTA mean reduce,
//     fused color jitter (alpha*x+beta*gray+delta*S) + optional 3x3 blur
//     (direct taps on padded plane) + erase/grid bitmasks + clamp ->
//     d_out in place. 53KB smem, 256 thr, 4 CTAs/SM, ONE barrier.
// Randomness replicates JAX Threefry-2x32, threefry_partitionable=True.
// ============================================================================

#define NT 256
#define BATCH 2048
#define HWpx 4096
#define CHW 12288
// kernel A staging
#define RGSTRIDE 136              // floats per RG row (68 px * 2)
#define OFF_B (68 * 136)          // 9248
#define BSTRIDE 68
#define A_FLOATS (OFF_B + 68 * 68)   // 13872 floats = 55488 B
// kernel B padded warped planes
#define PSTR 68
#define PLANE (66 * 68)           // 4488 floats
#define B_FLOATS (3 * PLANE)      // 13464 floats = 53856 B

__device__ __forceinline__ uint32_t rotl32(uint32_t v, int d) {
    return (v << d) | (v >> (32 - d));
}

// Threefry-2x32, 20 rounds, exactly as in jax._src.prng
__device__ __forceinline__ void tf2x32(uint32_t k0, uint32_t k1,
                                       uint32_t x0, uint32_t x1,
                                       uint32_t &o0, uint32_t &o1) {
    const uint32_t ks2 = k0 ^ k1 ^ 0x1BD11BDAu;
    x0 += k0; x1 += k1;
#define TFR(r) { x0 += x1; x1 = rotl32(x1, (r)); x1 ^= x0; }
    TFR(13) TFR(15) TFR(26) TFR(6)   x0 += k1;  x1 += ks2 + 1u;
    TFR(17) TFR(29) TFR(16) TFR(24)  x0 += ks2; x1 += k0 + 2u;
    TFR(13) TFR(15) TFR(26) TFR(6)   x0 += k0;  x1 += k1 + 3u;
    TFR(17) TFR(29) TFR(16) TFR(24)  x0 += k1;  x1 += ks2 + 4u;
    TFR(13) TFR(15) TFR(26) TFR(6)   x0 += ks2; x1 += k0 + 5u;
#undef TFR
    o0 = x0; o1 = x1;
}

__device__ __forceinline__ uint32_t rb32(uint32_t k0, uint32_t k1, uint32_t idx) {
    uint32_t a, b; tf2x32(k0, k1, 0u, idx, a, b); return a ^ b;
}

__device__ __forceinline__ float u01f(uint32_t bits) {
    return __uint_as_float((bits >> 9) | 0x3f800000u) - 1.0f;
}
__device__ __forceinline__ float unif(uint32_t bits, float lo, float hi) {
    return fmaxf(lo, u01f(bits) * (hi - lo) + lo);
}

// ============================================================================
// Kernel A: affine warp + hflip
// ============================================================================
__global__ void __launch_bounds__(NT, 4)
warp_kernel(const float* __restrict__ gin, float* __restrict__ gout) {
    extern __shared__ float smem[];
    float* sRG = smem;             // 68 rows x 68 px x 2 (RG interleaved)
    float* sBp = smem + OFF_B;     // 68 rows x 68
    __shared__ float PA[7];        // m00,m01,m10,m11,tx,ty,flip
    __shared__ uint32_t K1a[4];
    __shared__ uint32_t K2a[8];
    __shared__ float Ua[6];

    const int b = blockIdx.x;
    const int tid = threadIdx.x;

    // ---- params (warp 0): kg (affine) + kf (flip) ----
    if (tid < 32) {
        const int lane = tid;
        uint32_t o0, o1;
        if (lane < 2) {            // kg = split#0, kf = split#1
            tf2x32(0u, 42u, 0u, (uint32_t)lane, o0, o1);
            K1a[2 * lane] = o0; K1a[2 * lane + 1] = o1;
        }
        __syncwarp();
        if (lane < 4) {
            tf2x32(K1a[0], K1a[1], 0u, (uint32_t)lane, o0, o1);
            K2a[2 * lane] = o0; K2a[2 * lane + 1] = o1;
        }
        __syncwarp();
        const uint32_t ub = (uint32_t)b;
        const float DEG = (float)(3.14159265358979323846 / 180.0);
        switch (lane) {
            case 0: Ua[0] = unif(rb32(K2a[0], K2a[1], ub), -25.f, 25.f) * DEG; break;
            case 1: Ua[1] = unif(rb32(K2a[2], K2a[3], ub), -15.f, 15.f) * DEG; break;
            case 2: Ua[2] = unif(rb32(K2a[4], K2a[5], ub), 0.85f, 1.15f); break;
            case 3: Ua[3] = unif(rb32(K2a[6], K2a[7], 2u*ub),    -0.15f, 0.15f); break;
            case 4: Ua[4] = unif(rb32(K2a[6], K2a[7], 2u*ub+1u), -0.15f, 0.15f); break;
            case 5: Ua[5] = u01f(rb32(K1a[2], K1a[3], ub)); break;
            default: break;
        }
        __syncwarp();
        if (lane == 0) {
            float ang = Ua[0], shr = Ua[1], scl = Ua[2];
            float c = cosf(ang), s = sinf(ang), t = tanf(shr);
            PA[0] = (c - t * (-s)) / scl;
            PA[1] = (s - t * c) / scl;
            PA[2] = (-s) / scl;
            PA[3] = c / scl;
            PA[4] = Ua[3] * 64.0f;
            PA[5] = Ua[4] * 64.0f;
            PA[6] = (Ua[5] < 0.6f) ? 1.0f : 0.0f;
        }
    }

    // ---- zero both planes ----
    {
        float4* s4 = (float4*)smem;
        const float4 z = make_float4(0.f, 0.f, 0.f, 0.f);
        #pragma unroll
        for (int i = tid; i < A_FLOATS / 4; i += NT) s4[i] = z;
    }
    __syncthreads();

    // ---- interior load: planar global -> RG + B planes ----
    {
        const float4* gin4 = (const float4*)(gin + (size_t)b * CHW);
        #pragma unroll
        for (int j = 0; j < 4; j++) {
            int q = tid + j * NT;               // 0..1023, 4px quads
            float4 R4 = gin4[q];
            float4 G4 = gin4[q + 1024];
            float4 B4 = gin4[q + 2048];
            int h = q >> 4, w = (q & 15) << 2;
            int rgbase = ((h + 2) * 68 + (w + 2)) * 2;
            *(float4*)(sRG + rgbase)     = make_float4(R4.x, G4.x, R4.y, G4.y);
            *(float4*)(sRG + rgbase + 4) = make_float4(R4.z, G4.z, R4.w, G4.w);
            float* pb = sBp + (h + 2) * BSTRIDE + (w + 2);
            pb[0] = B4.x; pb[1] = B4.y; pb[2] = B4.z; pb[3] = B4.w;
        }
    }
    __syncthreads();

    // ---- gather + flip -> gout (planar, float4 stores) ----
    const float m00 = PA[0], m01 = PA[1], m10 = PA[2], m11 = PA[3];
    const float tx = PA[4], ty = PA[5];
    const bool flip = (PA[6] != 0.0f);
    float* o = gout + (size_t)b * CHW;
    #pragma unroll
    for (int j = 0; j < 4; j++) {
        int q = tid + j * NT;
        int h = q >> 4, wb = (q & 15) << 2;
        float gy = (float)h - 31.5f;
        float gx = (float)wb - 31.5f;
        float sx = m00 * gx + m01 * gy - tx + 31.5f;
        float sy = m10 * gx + m11 * gy - ty + 31.5f;
        float vr[4], vg[4], vb[4];
        #pragma unroll
        for (int k = 0; k < 4; k++) {
            float x0f = floorf(sx), y0f = floorf(sy);
            float wx = sx - x0f, wy = sy - y0f;
            int xi = min(max((int)x0f, -2), 64);
            int yi = min(max((int)y0f, -2), 64);
            const float* pRG = sRG + ((yi + 2) * 68 + (xi + 2)) * 2;
            const float* pB  = sBp + (yi + 2) * BSTRIDE + (xi + 2);
            float2 t00 = *(const float2*)(pRG);
            float2 t01 = *(const float2*)(pRG + 2);
            float2 t10 = *(const float2*)(pRG + RGSTRIDE);
            float2 t11 = *(const float2*)(pRG + RGSTRIDE + 2);
            float b00 = pB[0], b01 = pB[1], b10 = pB[BSTRIDE], b11 = pB[BSTRIDE + 1];
            float w11 = wx * wy;
            float w01 = wx - w11;
            float w10 = wy - w11;
            float w00 = 1.0f - wx - wy + w11;
            vr[k] = t00.x * w00 + t01.x * w01 + t10.x * w10 + t11.x * w11;
            vg[k] = t00.y * w00 + t01.y * w01 + t10.y * w10 + t11.y * w11;
            vb[k] = b00  * w00 + b01  * w01 + b10  * w10 + b11  * w11;
            sx += m00; sy += m10;
        }
        int colbase = flip ? (60 - wb) : wb;
        float4 R, G, Bv;
        if (flip) {
            R  = make_float4(vr[3], vr[2], vr[1], vr[0]);
            G  = make_float4(vg[3], vg[2], vg[1], vg[0]);
            Bv = make_float4(vb[3], vb[2], vb[1], vb[0]);
        } else {
            R  = make_float4(vr[0], vr[1], vr[2], vr[3]);
            G  = make_float4(vg[0], vg[1], vg[2], vg[3]);
            Bv = make_float4(vb[0], vb[1], vb[2], vb[3]);
        }
        float* op = o + h * 64 + colbase;
        *(float4*)(op)            = R;
        *(float4*)(op + HWpx)     = G;
        *(float4*)(op + 2 * HWpx) = Bv;
    }
}

// ============================================================================
// Kernel B: mean + color jitter + blur + erase + gridmask + clamp (in place)
// ============================================================================
struct PostParams {
    float br, ct, st;
    float top, bot, left, right;
    float gd, gl;
    uint32_t kv0, kv1;
    int blur, eapply, gapply;
};

__global__ void __launch_bounds__(NT, 4)
post_kernel(float* __restrict__ gio) {
    extern __shared__ float sW[];   // 3 planes, 66 rows x stride 68, 1px zero border
    __shared__ PostParams P;
    __shared__ float red[NT / 32];
    __shared__ uint32_t K1[12];
    __shared__ uint32_t K2[30];
    __shared__ float U[17];
    __shared__ uint32_t gm[2], er_row[2], er_col[2];

    const int b = blockIdx.x;
    const int tid = threadIdx.x;

    // ---- params (warp 0): kc, kb, ke, km ----
    if (tid < 32) {
        const int lane = tid;
        uint32_t o0, o1;
        if (lane < 6) {
            tf2x32(0u, 42u, 0u, (uint32_t)lane, o0, o1);
            K1[2 * lane] = o0; K1[2 * lane + 1] = o1;
        }
        __syncwarp();
        if (lane < 3) {            // kc -> 3
            tf2x32(K1[4], K1[5], 0u, (uint32_t)lane, o0, o1);
            K2[8 + 2 * lane] = o0; K2[9 + 2 * lane] = o1;
        } else if (lane < 9) {     // ke -> 6
            int i = lane - 3;
            tf2x32(K1[8], K1[9], 0u, (uint32_t)i, o0, o1);
            K2[14 + 2 * i] = o0; K2[15 + 2 * i] = o1;
        } else if (lane < 11) {    // km -> 2
            int i = lane - 9;
            tf2x32(K1[10], K1[11], 0u, (uint32_t)i, o0, o1);
            K2[26 + 2 * i] = o0; K2[27 + 2 * i] = o1;
        }
        __syncwarp();
        const uint32_t ub = (uint32_t)b;
        switch (lane) {
            case 6:  U[6]  = unif(rb32(K2[8],  K2[9],  ub), 0.7f, 1.3f); break;
            case 7:  U[7]  = unif(rb32(K2[10], K2[11], ub), 0.7f, 1.3f); break;
            case 8:  U[8]  = unif(rb32(K2[12], K2[13], ub), 0.8f, 1.2f); break;
            case 9:  U[9]  = u01f(rb32(K1[6],  K1[7],  ub)); break;
            case 10: U[10] = unif(rb32(K2[14], K2[15], ub), 0.02f, 0.1f); break;
            case 11: U[11] = unif(rb32(K2[16], K2[17], ub), 0.3f, 3.0f); break;
            case 12: U[12] = u01f(rb32(K2[18], K2[19], ub)); break;
            case 13: U[13] = u01f(rb32(K2[20], K2[21], ub)); break;
            case 14: U[14] = u01f(rb32(K2[24], K2[25], ub)); break;
            case 15: U[15] = floorf(unif(rb32(K2[26], K2[27], ub), 8.f, 32.f)); break;
            case 16: U[16] = u01f(rb32(K2[28], K2[29], ub)); break;
            default: break;
        }
        __syncwarp();
        if (lane == 0) {
            P.br = U[6]; P.ct = U[7]; P.st = U[8];
            P.blur = (U[9] < 0.3f);
            float area = (U[10] * 64.0f) * 64.0f;
            float ratio = U[11];
            float eh = fminf(fmaxf(sqrtf(area * ratio), 1.0f), 64.0f);
            float ew = fminf(fmaxf(sqrtf(area / ratio), 1.0f), 64.0f);
            P.top = U[12] * (64.0f - eh);   P.bot = P.top + eh;
            P.left = U[13] * (64.0f - ew);  P.right = P.left + ew;
            P.eapply = (U[14] < 0.3f);
            P.gd = U[15]; P.gl = floorf(U[15] * 0.6f);
            P.gapply = (U[16] < 0.3f);
            P.kv0 = K2[22]; P.kv1 = K2[23];
        }
        __syncwarp();
        {
            float c0 = (float)lane, c1 = (float)(lane + 32);
            float gd = P.gd, gl = P.gl;
            uint32_t g0 = __ballot_sync(0xffffffffu, fmodf(c0, gd) < gl);
            uint32_t g1 = __ballot_sync(0xffffffffu, fmodf(c1, gd) < gl);
            uint32_t r0 = __ballot_sync(0xffffffffu, c0 >= P.top && c0 < P.bot);
            uint32_t r1 = __ballot_sync(0xffffffffu, c1 >= P.top && c1 < P.bot);
            uint32_t q0 = __ballot_sync(0xffffffffu, c0 >= P.left && c0 < P.right);
            uint32_t q1 = __ballot_sync(0xffffffffu, c1 >= P.left && c1 < P.right);
            if (lane == 0) {
                gm[0] = g0; gm[1] = g1;
                er_row[0] = r0; er_row[1] = r1;
                er_col[0] = q0; er_col[1] = q1;
            }
        }
    }

    // ---- zero 1px borders (792 cells, one per thread tid<792... NT=256 so loop) ----
    #pragma unroll
    for (int i = tid; i < 792; i += NT) {
        int plane = i / 264;
        int r = i - plane * 264;
        int row, col;
        if (r < 136) { row = (r < 68) ? 0 : 65; col = (r < 68) ? r : r - 68; }
        else { int r2 = r - 136; row = 1 + (r2 >> 1); col = (r2 & 1) ? 65 : 0; }
        sW[plane * PLANE + row * PSTR + col] = 0.f;
    }

    // ---- load warped sample (float4) into padded planes + sum ----
    float lsum = 0.f;
    {
        const float4* g4 = (const float4*)(gio + (size_t)b * CHW);
        #pragma unroll
        for (int j = 0; j < 12; j++) {
            int q = tid + j * NT;             // 0..3071
            float4 v = g4[q];
            int c = q >> 10;
            int p4 = q & 1023;
            int h = p4 >> 4, w = (p4 & 15) << 2;
            float* p = sW + c * PLANE + (h + 1) * PSTR + (w + 1);
            p[0] = v.x; p[1] = v.y; p[2] = v.z; p[3] = v.w;
            lsum += v.x + v.y + v.z + v.w;
        }
    }
    #pragma unroll
    for (int off = 16; off > 0; off >>= 1)
        lsum += __shfl_xor_sync(0xffffffffu, lsum, off);
    if ((tid & 31) == 0) red[tid >> 5] = lsum;
    __syncthreads();

    // ---- per-warp mean finish ----
    float alpha, beta, delta;
    {
        const int lane = tid & 31;
        float t = (lane < NT / 32) ? red[lane] : 0.f;
        #pragma unroll
        for (int off = 4; off > 0; off >>= 1)
            t += __shfl_xor_sync(0xffffffffu, t, off);
        t = __shfl_sync(0xffffffffu, t, 0);
        float mean = (P.br * t) * (1.0f / 12288.0f);
        float bc = P.br * P.ct;
        alpha = P.st * bc;
        beta  = (1.0f - P.st) * bc;
        delta = mean * (1.0f - P.ct);
    }
    const bool doblur = P.blur;
    const bool eap = P.eapply, gap = P.gapply;
    const uint32_t kv0 = P.kv0, kv1 = P.kv1;
    float* o = gio + (size_t)b * CHW;

    #pragma unroll
    for (int j = 0; j < 4; j++) {
        int q = tid + j * NT;
        int h = q >> 4, wb = (q & 15) << 2;
        const int base = h * 64 + wb;
        const bool ghit_h = gap && ((gm[h >> 5] >> (h & 31)) & 1u);
        const bool ehit_h = eap && ((er_row[h >> 5] >> (h & 31)) & 1u);
        float vr[4], vg[4], vb[4], Sv[4];
        if (!doblur) {
            #pragma unroll
            for (int c = 0; c < 3; c++) {
                const float* p = sW + c * PLANE + (h + 1) * PSTR + (wb + 1);
                #pragma unroll
                for (int k = 0; k < 4; k++) {
                    float v = p[k];
                    if (c == 0) vr[k] = v; else if (c == 1) vg[k] = v; else vb[k] = v;
                }
            }
            Sv[0] = Sv[1] = Sv[2] = Sv[3] = 1.0f;
        } else {
            #pragma unroll
            for (int c = 0; c < 3; c++) {
                const float* p = sW + c * PLANE + h * PSTR + wb;  // top-left of 3x6 window
                float hb0[4], hb1[4], hb2[4];
                #pragma unroll
                for (int k = 0; k < 4; k++) {
                    hb0[k] = 0.25f * (p[k] + p[k + 2]) + 0.5f * p[k + 1];
                    hb1[k] = 0.25f * (p[PSTR + k] + p[PSTR + k + 2]) + 0.5f * p[PSTR + k + 1];
                    hb2[k] = 0.25f * (p[2 * PSTR + k] + p[2 * PSTR + k + 2]) + 0.5f * p[2 * PSTR + k + 1];
                }
                #pragma unroll
                for (int k = 0; k < 4; k++) {
                    float v = 0.25f * (hb0[k] + hb2[k]) + 0.5f * hb1[k];
                    if (c == 0) vr[k] = v; else if (c == 1) vg[k] = v; else vb[k] = v;
                }
            }
            float ry = 1.0f - 0.25f * ((h == 0) + (h == 63));
            #pragma unroll
            for (int k = 0; k < 4; k++) {
                int w = wb + k;
                Sv[k] = ry * (1.0f - 0.25f * ((w == 0) + (w == 63)));
            }
        }
        float4 O0, O1, O2;
        float* O0p = &O0.x; float* O1p = &O1.x; float* O2p = &O2.x;
        #pragma unroll
        for (int k = 0; k < 4; k++) {
            int w = wb + k;
            float r = vr[k], g = vg[k], bl = vb[k];
            float gray = 0.299f * r + 0.587f * g + 0.114f * bl;
            float dd = delta * Sv[k];
            float v0 = alpha * r  + beta * gray + dd;
            float v1 = alpha * g  + beta * gray + dd;
            float v2 = alpha * bl + beta * gray + dd;
            if (ehit_h && ((er_col[w >> 5] >> (w & 31)) & 1u)) {
                uint32_t rbase = ((uint32_t)b * 3u) * 4096u + (uint32_t)(base + k);
                v0 = u01f(rb32(kv0, kv1, rbase));
                v1 = u01f(rb32(kv0, kv1, rbase + 4096u));
                v2 = u01f(rb32(kv0, kv1, rbase + 8192u));
            }
            if (ghit_h && ((gm[w >> 5] >> (w & 31)) & 1u)) {
                v0 = 0.f; v1 = 0.f; v2 = 0.f;
            }
            O0p[k] = fminf(fmaxf(v0, 0.f), 1.f);
            O1p[k] = fminf(fmaxf(v1, 0.f), 1.f);
            O2p[k] = fminf(fmaxf(v2, 0.f), 1.f);
        }
        *(float4*)(o + base)            = O0;
        *(float4*)(o + HWpx + base)     = O1;
        *(float4*)(o + 2 * HWpx + base) = O2;
    }
}

extern "C" void kernel_launch(void* const* d_in, const int* in_sizes, int n_in,
                              void* d_out, int out_size) {
    (void)in_sizes; (void)n_in; (void)out_size;
    const float* x = (const float*)d_in[0];
    float* out = (float*)d_out;
    cudaFuncSetAttribute(warp_kernel, cudaFuncAttributeMaxDynamicSharedMemorySize,
                         A_FLOATS * (int)sizeof(float));
    cudaFuncSetAttribute(post_kernel, cudaFuncAttributeMaxDynamicSharedMemorySize,
                         B_FLOATS * (int)sizeof(float));
    warp_kernel<<<BATCH, NT, A_FLOATS * sizeof(float)>>>(x, out);
    post_kernel<<<BATCH, NT, B_FLOATS * sizeof(float)>>>(out);
}

// round 6
// speedup vs baseline: 1.0443x; 1.0443x over previous
#include <cuda_runtime.h>
#include <stdint.h>

// ============================================================================
// EnhancedAntiOverfittingAugmentation — round 6: single kernel, 4 CTAs/SM.
//  - staging: RG-interleaved + B planes, 2px zero border (55.5KB)
//  - non-blur CTAs: sum pass, then recompute gather fused with jitter/masks
//    (no intermediate traffic at all)
//  - blur CTAs: warped -> gout (L2-resident round trip) -> SMEM (reusing dead
//    staging) -> 3x3 blur + jitter/masks
//  - uniform-control-flow table-driven Threefry param generation
// Randomness replicates JAX Threefry-2x32, threefry_partitionable=True.
// ============================================================================

#define NT 256
#define BATCH 2048
#define HWpx 4096
#define CHW 12288
#define RGSTRIDE 136              // floats per RG row (68 px * 2)
#define OFF_B (68 * 136)          // 9248
#define BSTRIDE 68
#define STAGE_FLOATS (OFF_B + 68 * 68)   // 13872 floats = 55488 B
// blur readback planes (overlay on staging after it dies)
#define PSTR 68
#define PLANE (66 * 68)           // 4488

__constant__ int   c_parent[16] = {0,0,0,0, 2,2,2, 4,4,4,4,4,4, 5,5, 0};
__constant__ int   c_child[16]  = {0,1,2,3, 0,1,2, 0,1,2,3,4,5, 0,1, 0};
__constant__ int   c_src[17]    = {6,7,8,9,9, 1, 10,11,12, 3, 13,14,15,16, 18, 19, 20};
__constant__ int   c_cnt[17]    = {0,0,0,1,2, 0, 0,0,0, 0, 0,0,0,0, 0, 0, 0};
__constant__ float c_lo[17]  = {-25.f,-15.f,0.85f,-0.15f,-0.15f, 0.f, 0.7f,0.7f,0.8f,
                                0.f, 0.02f,0.3f,0.f,0.f, 0.f, 8.f, 0.f};
__constant__ float c_hi[17]  = {25.f,15.f,1.15f,0.15f,0.15f, 1.f, 1.3f,1.3f,1.2f,
                                1.f, 0.1f,3.0f,1.f,1.f, 1.f, 32.f, 1.f};
#define DEGf 0.017453292519943295f
__constant__ float c_mul[17] = {DEGf,DEGf,1.f,1.f,1.f, 1.f, 1.f,1.f,1.f,
                                1.f, 1.f,1.f,1.f,1.f, 1.f, 1.f, 1.f};

__device__ __forceinline__ uint32_t rotl32(uint32_t v, int d) {
    return (v << d) | (v >> (32 - d));
}

// Threefry-2x32, 20 rounds, exactly as in jax._src.prng
__device__ __forceinline__ void tf2x32(uint32_t k0, uint32_t k1,
                                       uint32_t x0, uint32_t x1,
                                       uint32_t &o0, uint32_t &o1) {
    const uint32_t ks2 = k0 ^ k1 ^ 0x1BD11BDAu;
    x0 += k0; x1 += k1;
#define TFR(r) { x0 += x1; x1 = rotl32(x1, (r)); x1 ^= x0; }
    TFR(13) TFR(15) TFR(26) TFR(6)   x0 += k1;  x1 += ks2 + 1u;
    TFR(17) TFR(29) TFR(16) TFR(24)  x0 += ks2; x1 += k0 + 2u;
    TFR(13) TFR(15) TFR(26) TFR(6)   x0 += k0;  x1 += k1 + 3u;
    TFR(17) TFR(29) TFR(16) TFR(24)  x0 += k1;  x1 += ks2 + 4u;
    TFR(13) TFR(15) TFR(26) TFR(6)   x0 += ks2; x1 += k0 + 5u;
#undef TFR
    o0 = x0; o1 = x1;
}

__device__ __forceinline__ uint32_t rb32(uint32_t k0, uint32_t k1, uint32_t idx) {
    uint32_t a, b; tf2x32(k0, k1, 0u, idx, a, b); return a ^ b;
}

__device__ __forceinline__ float u01f(uint32_t bits) {
    return __uint_as_float((bits >> 9) | 0x3f800000u) - 1.0f;
}
__device__ __forceinline__ float unif(uint32_t bits, float lo, float hi) {
    return fmaxf(lo, u01f(bits) * (hi - lo) + lo);
}

struct SampleParams {
    float m00, m01, m10, m11, tx, ty;
    float br, ct, st;
    float top, bot, left, right;
    float gd, gl;
    uint32_t kv0, kv1;
    int flip, blur, eapply, gapply;
};

__global__ void __launch_bounds__(NT, 4)
aug_kernel(const float* __restrict__ gin, float* __restrict__ gout) {
    extern __shared__ float smem[];
    float* sRG = smem;             // 68x68x2 RG interleaved (pad 2)
    float* sBp = smem + OFF_B;     // 68x68 B plane (pad 2)
    float* sW  = smem;             // blur path: 3 planes 66x(stride 68), 1px pad
    __shared__ SampleParams P;
    __shared__ float red[NT / 32];
    __shared__ uint32_t K[42];     // pairs: 0..5 = level1 keys, 6..20 = level2
    __shared__ float U[17];
    __shared__ uint32_t gm[2], er_row[2], er_col[2];

    const int b = blockIdx.x;
    const int tid = threadIdx.x;

    // ================= params, uniform control flow (warp 0) =================
    if (tid < 32) {
        const int lane = tid;
        const uint32_t ub = (uint32_t)b;
        uint32_t o0, o1;
        // level 1: split(key(42), 6)
        tf2x32(0u, 42u, 0u, (uint32_t)min(lane, 5), o0, o1);
        if (lane < 6) { K[2 * lane] = o0; K[2 * lane + 1] = o1; }
        __syncwarp();
        // level 2: 15 child splits, table-driven
        {
            int li = min(lane, 15);
            int p = c_parent[li];
            tf2x32(K[2 * p], K[2 * p + 1], 0u, (uint32_t)c_child[li], o0, o1);
            if (lane < 15) { K[12 + 2 * lane] = o0; K[13 + 2 * lane] = o1; }
        }
        __syncwarp();
        // 17 uniforms, table-driven, single warp-wide Threefry
        {
            int li = min(lane, 16);
            int s = c_src[li];
            int cs = c_cnt[li];
            uint32_t cnt = (cs == 0) ? ub : ((cs == 1) ? 2u * ub : 2u * ub + 1u);
            uint32_t bits = rb32(K[2 * s], K[2 * s + 1], cnt);
            float u = unif(bits, c_lo[li], c_hi[li]) * c_mul[li];
            if (lane == 15) u = floorf(u);
            if (lane < 17) U[lane] = u;
        }
        __syncwarp();
        // derived params: all lanes compute redundantly (uniform), lane 0 writes
        {
            float ang = U[0], shr = U[1], scl = U[2];
            float cc = cosf(ang), ss = sinf(ang), t = tanf(shr);
            float m00 = (cc - t * (-ss)) / scl;
            float m01 = (ss - t * cc) / scl;
            float m10 = (-ss) / scl;
            float m11 = cc / scl;
            float area = (U[10] * 64.0f) * 64.0f;
            float ratio = U[11];
            float eh = fminf(fmaxf(sqrtf(area * ratio), 1.0f), 64.0f);
            float ew = fminf(fmaxf(sqrtf(area / ratio), 1.0f), 64.0f);
            float top = U[12] * (64.0f - eh);
            float left = U[13] * (64.0f - ew);
            if (lane == 0) {
                P.m00 = m00; P.m01 = m01; P.m10 = m10; P.m11 = m11;
                P.tx = U[3] * 64.0f;  P.ty = U[4] * 64.0f;
                P.flip = (U[5] < 0.6f);
                P.br = U[6]; P.ct = U[7]; P.st = U[8];
                P.blur = (U[9] < 0.3f);
                P.top = top; P.bot = top + eh;
                P.left = left; P.right = left + ew;
                P.eapply = (U[14] < 0.3f);
                P.gd = U[15]; P.gl = floorf(U[15] * 0.6f);
                P.gapply = (U[16] < 0.3f);
                P.kv0 = K[34]; P.kv1 = K[35];   // ke split #4 (value key)
            }
            __syncwarp();
            // bitmasks (grid row==col mask since H==W)
            float c0 = (float)lane, c1 = (float)(lane + 32);
            float gd = U[15], gl = floorf(U[15] * 0.6f);
            uint32_t g0 = __ballot_sync(0xffffffffu, fmodf(c0, gd) < gl);
            uint32_t g1 = __ballot_sync(0xffffffffu, fmodf(c1, gd) < gl);
            uint32_t r0 = __ballot_sync(0xffffffffu, c0 >= top && c0 < top + eh);
            uint32_t r1 = __ballot_sync(0xffffffffu, c1 >= top && c1 < top + eh);
            uint32_t q0 = __ballot_sync(0xffffffffu, c0 >= left && c0 < left + ew);
            uint32_t q1 = __ballot_sync(0xffffffffu, c1 >= left && c1 < left + ew);
            if (lane == 0) {
                gm[0] = g0; gm[1] = g1;
                er_row[0] = r0; er_row[1] = r1;
                er_col[0] = q0; er_col[1] = q1;
            }
        }
    }

    // ================= border zeroing of staging planes ======================
    // RG: full rows {0,1,66,67} (136 float4) + side cols rows 2..65 (128 float4)
    #pragma unroll
    for (int i = tid; i < 264; i += NT) {
        int addr;
        if (i < 136) {
            int r = i / 34, c4 = i % 34;
            int row = (r < 2) ? r : 64 + r;
            addr = row * RGSTRIDE + c4 * 4;
        } else {
            int j = i - 136;
            int r = 2 + (j >> 1);
            addr = r * RGSTRIDE + ((j & 1) ? 132 : 0);
        }
        *(float4*)(smem + addr) = make_float4(0.f, 0.f, 0.f, 0.f);
    }
    // B: full rows (68 float4) + side cols (128 float2)
    #pragma unroll
    for (int i = tid; i < 68; i += NT) {
        int r = i / 17, c4 = i % 17;
        int row = (r < 2) ? r : 64 + r;
        *(float4*)(sBp + row * BSTRIDE + c4 * 4) = make_float4(0.f, 0.f, 0.f, 0.f);
    }
    #pragma unroll
    for (int i = tid; i < 128; i += NT) {
        int r = 2 + (i >> 1);
        int col = (i & 1) ? 66 : 0;
        *(float2*)(sBp + r * BSTRIDE + col) = make_float2(0.f, 0.f);
    }

    // ================= interior load: planar global -> RG + B ================
    {
        const float4* gin4 = (const float4*)(gin + (size_t)b * CHW);
        #pragma unroll
        for (int j = 0; j < 4; j++) {
            int q = tid + j * NT;               // 0..1023 quads
            float4 R4 = gin4[q];
            float4 G4 = gin4[q + 1024];
            float4 B4 = gin4[q + 2048];
            int h = q >> 4, w = (q & 15) << 2;
            int rgbase = ((h + 2) * 68 + (w + 2)) * 2;
            *(float4*)(sRG + rgbase)     = make_float4(R4.x, G4.x, R4.y, G4.y);
            *(float4*)(sRG + rgbase + 4) = make_float4(R4.z, G4.z, R4.w, G4.w);
            float* pb = sBp + (h + 2) * BSTRIDE + (w + 2);
            pb[0] = B4.x; pb[1] = B4.y; pb[2] = B4.z; pb[3] = B4.w;
        }
    }
    __syncthreads();

    // ================= phase 1: gather (sum; blur CTAs also store) ===========
    const float m00 = P.m00, m01 = P.m01, m10 = P.m10, m11 = P.m11;
    const float tx = P.tx, ty = P.ty;
    const bool flip = P.flip;
    const bool doblur = P.blur;
    float* o = gout + (size_t)b * CHW;
    float lsum = 0.f;

    #pragma unroll
    for (int j = 0; j < 4; j++) {
        int q = tid + j * NT;
        int h = q >> 4, wb = (q & 15) << 2;
        float gy = (float)h - 31.5f;
        float gx = (float)wb - 31.5f;
        float sx = m00 * gx + m01 * gy - tx + 31.5f;
        float sy = m10 * gx + m11 * gy - ty + 31.5f;
        float vr[4], vg[4], vb[4];
        #pragma unroll
        for (int k = 0; k < 4; k++) {
            float x0f = floorf(sx), y0f = floorf(sy);
            float wx = sx - x0f, wy = sy - y0f;
            int xi = min(max((int)x0f, -2), 64);
            int yi = min(max((int)y0f, -2), 64);
            const float* pRG = sRG + ((yi + 2) * 68 + (xi + 2)) * 2;
            const float* pB  = sBp + (yi + 2) * BSTRIDE + (xi + 2);
            float2 t00 = *(const float2*)(pRG);
            float2 t01 = *(const float2*)(pRG + 2);
            float2 t10 = *(const float2*)(pRG + RGSTRIDE);
            float2 t11 = *(const float2*)(pRG + RGSTRIDE + 2);
            float b00 = pB[0], b01 = pB[1], b10 = pB[BSTRIDE], b11 = pB[BSTRIDE + 1];
            float w11 = wx * wy;
            float w01 = wx - w11;
            float w10 = wy - w11;
            float w00 = 1.0f - wx - wy + w11;
            vr[k] = t00.x * w00 + t01.x * w01 + t10.x * w10 + t11.x * w11;
            vg[k] = t00.y * w00 + t01.y * w01 + t10.y * w10 + t11.y * w11;
            vb[k] = b00  * w00 + b01  * w01 + b10  * w10 + b11  * w11;
            lsum += vr[k] + vg[k] + vb[k];
            sx += m00; sy += m10;
        }
        if (doblur) {
            int colbase = flip ? (60 - wb) : wb;
            float4 R, G, Bv;
            if (flip) {
                R  = make_float4(vr[3], vr[2], vr[1], vr[0]);
                G  = make_float4(vg[3], vg[2], vg[1], vg[0]);
                Bv = make_float4(vb[3], vb[2], vb[1], vb[0]);
            } else {
                R  = make_float4(vr[0], vr[1], vr[2], vr[3]);
                G  = make_float4(vg[0], vg[1], vg[2], vg[3]);
                Bv = make_float4(vb[0], vb[1], vb[2], vb[3]);
            }
            float* op = o + h * 64 + colbase;
            *(float4*)(op)            = R;
            *(float4*)(op + HWpx)     = G;
            *(float4*)(op + 2 * HWpx) = Bv;
        }
    }
    #pragma unroll
    for (int off = 16; off > 0; off >>= 1)
        lsum += __shfl_xor_sync(0xffffffffu, lsum, off);
    if ((tid & 31) == 0) red[tid >> 5] = lsum;
    __syncthreads();

    // ---------------- per-warp mean finish ----------------
    float alpha, beta, delta;
    {
        const int lane = tid & 31;
        float t = (lane < NT / 32) ? red[lane] : 0.f;
        #pragma unroll
        for (int off = 4; off > 0; off >>= 1)
            t += __shfl_xor_sync(0xffffffffu, t, off);
        t = __shfl_sync(0xffffffffu, t, 0);
        float mean = (P.br * t) * (1.0f / 12288.0f);
        float bc = P.br * P.ct;
        alpha = P.st * bc;
        beta  = (1.0f - P.st) * bc;
        delta = mean * (1.0f - P.ct);
    }
    const bool eap = P.eapply, gap = P.gapply;
    const uint32_t kv0 = P.kv0, kv1 = P.kv1;

    if (!doblur) {
        // ========== phase 2 (non-blur): recompute gather + jitter + masks ====
        #pragma unroll
        for (int j = 0; j < 4; j++) {
            int q = tid + j * NT;
            int h = q >> 4, wb = (q & 15) << 2;
            const int base = h * 64 + wb;
            const bool ghit_h = gap && ((gm[h >> 5] >> (h & 31)) & 1u);
            const bool ehit_h = eap && ((er_row[h >> 5] >> (h & 31)) & 1u);
            const float gy = (float)h - 31.5f;
            float4 O0, O1, O2;
            float* O0p = &O0.x; float* O1p = &O1.x; float* O2p = &O2.x;
            #pragma unroll
            for (int k = 0; k < 4; k++) {
                int w = wb + k;
                int wsrc = flip ? (63 - w) : w;
                float gx = (float)wsrc - 31.5f;
                float sx = m00 * gx + m01 * gy - tx + 31.5f;
                float sy = m10 * gx + m11 * gy - ty + 31.5f;
                float x0f = floorf(sx), y0f = floorf(sy);
                float wx = sx - x0f, wy = sy - y0f;
                int xi = min(max((int)x0f, -2), 64);
                int yi = min(max((int)y0f, -2), 64);
                const float* pRG = sRG + ((yi + 2) * 68 + (xi + 2)) * 2;
                const float* pB  = sBp + (yi + 2) * BSTRIDE + (xi + 2);
                float2 t00 = *(const float2*)(pRG);
                float2 t01 = *(const float2*)(pRG + 2);
                float2 t10 = *(const float2*)(pRG + RGSTRIDE);
                float2 t11 = *(const float2*)(pRG + RGSTRIDE + 2);
                float b00 = pB[0], b01 = pB[1], b10 = pB[BSTRIDE], b11 = pB[BSTRIDE + 1];
                float w11 = wx * wy;
                float w01 = wx - w11;
                float w10 = wy - w11;
                float w00 = 1.0f - wx - wy + w11;
                float r  = t00.x * w00 + t01.x * w01 + t10.x * w10 + t11.x * w11;
                float g  = t00.y * w00 + t01.y * w01 + t10.y * w10 + t11.y * w11;
                float bl = b00  * w00 + b01  * w01 + b10  * w10 + b11  * w11;
                float gray = 0.299f * r + 0.587f * g + 0.114f * bl;
                float v0 = alpha * r  + beta * gray + delta;
                float v1 = alpha * g  + beta * gray + delta;
                float v2 = alpha * bl + beta * gray + delta;
                if (ehit_h && ((er_col[w >> 5] >> (w & 31)) & 1u)) {
                    uint32_t rbase = ((uint32_t)b * 3u) * 4096u + (uint32_t)(base + k);
                    v0 = u01f(rb32(kv0, kv1, rbase));
                    v1 = u01f(rb32(kv0, kv1, rbase + 4096u));
                    v2 = u01f(rb32(kv0, kv1, rbase + 8192u));
                }
                if (ghit_h && ((gm[w >> 5] >> (w & 31)) & 1u)) {
                    v0 = 0.f; v1 = 0.f; v2 = 0.f;
                }
                O0p[k] = fminf(fmaxf(v0, 0.f), 1.f);
                O1p[k] = fminf(fmaxf(v1, 0.f), 1.f);
                O2p[k] = fminf(fmaxf(v2, 0.f), 1.f);
            }
            *(float4*)(o + base)            = O0;
            *(float4*)(o + HWpx + base)     = O1;
            *(float4*)(o + 2 * HWpx + base) = O2;
        }
    } else {
        // ========== phase 2 (blur): readback -> padded SMEM -> blur + jitter =
        // zero 1px borders of the 3 warped planes (overlaying dead staging)
        #pragma unroll
        for (int i = tid; i < 792; i += NT) {
            int plane = i / 264;
            int r = i - plane * 264;
            int row, col;
            if (r < 136) { row = (r < 68) ? 0 : 65; col = (r < 68) ? r : r - 68; }
            else { int r2 = r - 136; row = 1 + (r2 >> 1); col = (r2 & 1) ? 65 : 0; }
            sW[plane * PLANE + row * PSTR + col] = 0.f;
        }
        // readback warped sample (L2-hit) into padded planes
        {
            const float4* g4 = (const float4*)o;
            #pragma unroll
            for (int j = 0; j < 12; j++) {
                int q = tid + j * NT;             // 0..3071
                float4 v = g4[q];
                int c = q >> 10;
                int p4 = q & 1023;
                int h = p4 >> 4, w = (p4 & 15) << 2;
                float* p = sW + c * PLANE + (h + 1) * PSTR + (w + 1);
                p[0] = v.x; p[1] = v.y; p[2] = v.z; p[3] = v.w;
            }
        }
        __syncthreads();

        #pragma unroll
        for (int j = 0; j < 4; j++) {
            int q = tid + j * NT;
            int h = q >> 4, wb = (q & 15) << 2;
            const int base = h * 64 + wb;
            const bool ghit_h = gap && ((gm[h >> 5] >> (h & 31)) & 1u);
            const bool ehit_h = eap && ((er_row[h >> 5] >> (h & 31)) & 1u);
            float vr[4], vg[4], vb[4], Sv[4];
            #pragma unroll
            for (int c = 0; c < 3; c++) {
                const float* p = sW + c * PLANE + h * PSTR + wb;  // 3x6 window TL
                float hb0[4], hb1[4], hb2[4];
                #pragma unroll
                for (int k = 0; k < 4; k++) {
                    hb0[k] = 0.25f * (p[k] + p[k + 2]) + 0.5f * p[k + 1];
                    hb1[k] = 0.25f * (p[PSTR + k] + p[PSTR + k + 2]) + 0.5f * p[PSTR + k + 1];
                    hb2[k] = 0.25f * (p[2 * PSTR + k] + p[2 * PSTR + k + 2]) + 0.5f * p[2 * PSTR + k + 1];
                }
                #pragma unroll
                for (int k = 0; k < 4; k++) {
                    float v = 0.25f * (hb0[k] + hb2[k]) + 0.5f * hb1[k];
                    if (c == 0) vr[k] = v; else if (c == 1) vg[k] = v; else vb[k] = v;
                }
            }
            float ry = 1.0f - 0.25f * ((h == 0) + (h == 63));
            #pragma unroll
            for (int k = 0; k < 4; k++) {
                int w = wb + k;
                Sv[k] = ry * (1.0f - 0.25f * ((w == 0) + (w == 63)));
            }
            float4 O0, O1, O2;
            float* O0p = &O0.x; float* O1p = &O1.x; float* O2p = &O2.x;
            #pragma unroll
            for (int k = 0; k < 4; k++) {
                int w = wb + k;
                float r = vr[k], g = vg[k], bl = vb[k];
                float gray = 0.299f * r + 0.587f * g + 0.114f * bl;
                float dd = delta * Sv[k];
                float v0 = alpha * r  + beta * gray + dd;
                float v1 = alpha * g  + beta * gray + dd;
                float v2 = alpha * bl + beta * gray + dd;
                if (ehit_h && ((er_col[w >> 5] >> (w & 31)) & 1u)) {
                    uint32_t rbase = ((uint32_t)b * 3u) * 4096u + (uint32_t)(base + k);
                    v0 = u01f(rb32(kv0, kv1, rbase));
                    v1 = u01f(rb32(kv0, kv1, rbase + 4096u));
                    v2 = u01f(rb32(kv0, kv1, rbase + 8192u));
                }
                if (ghit_h && ((gm[w >> 5] >> (w & 31)) & 1u)) {
                    v0 = 0.f; v1 = 0.f; v2 = 0.f;
                }
                O0p[k] = fminf(fmaxf(v0, 0.f), 1.f);
                O1p[k] = fminf(fmaxf(v1, 0.f), 1.f);
                O2p[k] = fminf(fmaxf(v2, 0.f), 1.f);
            }
            *(float4*)(o + base)            = O0;
            *(float4*)(o + HWpx + base)     = O1;
            *(float4*)(o + 2 * HWpx + base) = O2;
        }
    }
}

extern "C" void kernel_launch(void* const* d_in, const int* in_sizes, int n_in,
                              void* d_out, int out_size) {
    (void)in_sizes; (void)n_in; (void)out_size;
    const float* x = (const float*)d_in[0];
    float* out = (float*)d_out;
    cudaFuncSetAttribute(aug_kernel, cudaFuncAttributeMaxDynamicSharedMemorySize,
                         STAGE_FLOATS * (int)sizeof(float));
    aug_kernel<<<BATCH, NT, STAGE_FLOATS * sizeof(float)>>>(x, out);
}

// round 8
// speedup vs baseline: 1.7248x; 1.6517x over previous
#include <cuda_runtime.h>
#include <stdint.h>

// ============================================================================
// EnhancedAntiOverfittingAugmentation — round 8: register-resident warped img
// with alignment-safe RG-interleaved staging (fixes R7 misaligned float2).
//  - staging: RG interleaved (68x68x2, 8B-aligned taps) + B plane (stride 72)
//  - gather keeps warped px in registers (8 px x 3 ch per thread @ NT=512)
//  - non-blur CTAs (70%): regs -> jitter/masks -> out (no warped SMEM pass)
//  - blur CTAs (30%): regs -> SMEM overlay (staging dead) -> 9-tap -> out
//  - uniform table-driven Threefry param generation (warp 0)
// Randomness replicates JAX Threefry-2x32, threefry_partitionable=True.
// 512 thr, 56.6KB smem, 2 CTAs/SM.
// ============================================================================

#define NT 512
#define BATCH 2048
#define HWpx 4096
#define CHW 12288
#define RGSTRIDE 136              // floats per RG row (68 px * 2)
#define OFF_B (68 * 136)          // 9248
#define BSTRIDE 72
#define STAGE_FLOATS (OFF_B + 68 * BSTRIDE)   // 9248 + 4896 = 14144 floats
// blur overlay planes (1px pad), overlaid on dead staging (needs 13464 <= 14144)
#define WSTR 68
#define WPLANE (66 * 68)          // 4488

__constant__ int   c_parent[16] = {0,0,0,0, 2,2,2, 4,4,4,4,4,4, 5,5, 0};
__constant__ int   c_child[16]  = {0,1,2,3, 0,1,2, 0,1,2,3,4,5, 0,1, 0};
__constant__ int   c_src[17]    = {6,7,8,9,9, 1, 10,11,12, 3, 13,14,15,16, 18, 19, 20};
__constant__ int   c_cnt[17]    = {0,0,0,1,2, 0, 0,0,0, 0, 0,0,0,0, 0, 0, 0};
__constant__ float c_lo[17]  = {-25.f,-15.f,0.85f,-0.15f,-0.15f, 0.f, 0.7f,0.7f,0.8f,
                                0.f, 0.02f,0.3f,0.f,0.f, 0.f, 8.f, 0.f};
__constant__ float c_hi[17]  = {25.f,15.f,1.15f,0.15f,0.15f, 1.f, 1.3f,1.3f,1.2f,
                                1.f, 0.1f,3.0f,1.f,1.f, 1.f, 32.f, 1.f};
#define DEGf 0.017453292519943295f
__constant__ float c_mul[17] = {DEGf,DEGf,1.f,1.f,1.f, 1.f, 1.f,1.f,1.f,
                                1.f, 1.f,1.f,1.f,1.f, 1.f, 1.f, 1.f};

__device__ __forceinline__ uint32_t rotl32(uint32_t v, int d) {
    return (v << d) | (v >> (32 - d));
}

// Threefry-2x32, 20 rounds, exactly as in jax._src.prng
__device__ __forceinline__ void tf2x32(uint32_t k0, uint32_t k1,
                                       uint32_t x0, uint32_t x1,
                                       uint32_t &o0, uint32_t &o1) {
    const uint32_t ks2 = k0 ^ k1 ^ 0x1BD11BDAu;
    x0 += k0; x1 += k1;
#define TFR(r) { x0 += x1; x1 = rotl32(x1, (r)); x1 ^= x0; }
    TFR(13) TFR(15) TFR(26) TFR(6)   x0 += k1;  x1 += ks2 + 1u;
    TFR(17) TFR(29) TFR(16) TFR(24)  x0 += ks2; x1 += k0 + 2u;
    TFR(13) TFR(15) TFR(26) TFR(6)   x0 += k0;  x1 += k1 + 3u;
    TFR(17) TFR(29) TFR(16) TFR(24)  x0 += k1;  x1 += ks2 + 4u;
    TFR(13) TFR(15) TFR(26) TFR(6)   x0 += ks2; x1 += k0 + 5u;
#undef TFR
    o0 = x0; o1 = x1;
}

__device__ __forceinline__ uint32_t rb32(uint32_t k0, uint32_t k1, uint32_t idx) {
    uint32_t a, b; tf2x32(k0, k1, 0u, idx, a, b); return a ^ b;
}

__device__ __forceinline__ float u01f(uint32_t bits) {
    return __uint_as_float((bits >> 9) | 0x3f800000u) - 1.0f;
}
__device__ __forceinline__ float unif(uint32_t bits, float lo, float hi) {
    return fmaxf(lo, u01f(bits) * (hi - lo) + lo);
}

struct SampleParams {
    float m00, m01, m10, m11, tx, ty;
    float br, ct, st;
    uint32_t kv0, kv1;
    int flip, blur, eapply, gapply;
};

__global__ void __launch_bounds__(NT, 2)
aug_kernel(const float* __restrict__ gin, float* __restrict__ gout) {
    extern __shared__ float smem[];
    float* sRG = smem;             // 68x68x2 RG interleaved (pad 2)
    float* sBp = smem + OFF_B;     // 68 rows x stride 72 B plane (pad 2)
    __shared__ SampleParams P;
    __shared__ float red[NT / 32];
    __shared__ uint32_t K[42];
    __shared__ float U[17];
    __shared__ uint32_t gm[2], er_row[2], er_col[2];

    const int b = blockIdx.x;
    const int tid = threadIdx.x;

    // ================= params, uniform control flow (warp 0) =================
    if (tid < 32) {
        const int lane = tid;
        const uint32_t ub = (uint32_t)b;
        uint32_t o0, o1;
        tf2x32(0u, 42u, 0u, (uint32_t)min(lane, 5), o0, o1);
        if (lane < 6) { K[2 * lane] = o0; K[2 * lane + 1] = o1; }
        __syncwarp();
        {
            int li = min(lane, 15);
            int p = c_parent[li];
            tf2x32(K[2 * p], K[2 * p + 1], 0u, (uint32_t)c_child[li], o0, o1);
            if (lane < 15) { K[12 + 2 * lane] = o0; K[13 + 2 * lane] = o1; }
        }
        __syncwarp();
        {
            int li = min(lane, 16);
            int s = c_src[li];
            int cs = c_cnt[li];
            uint32_t cnt = (cs == 0) ? ub : ((cs == 1) ? 2u * ub : 2u * ub + 1u);
            uint32_t bits = rb32(K[2 * s], K[2 * s + 1], cnt);
            float u = unif(bits, c_lo[li], c_hi[li]) * c_mul[li];
            if (lane == 15) u = floorf(u);
            if (lane < 17) U[lane] = u;
        }
        __syncwarp();
        {
            float ang = U[0], shr = U[1], scl = U[2];
            float cc = cosf(ang), ss = sinf(ang), t = tanf(shr);
            float m00 = (cc - t * (-ss)) / scl;
            float m01 = (ss - t * cc) / scl;
            float m10 = (-ss) / scl;
            float m11 = cc / scl;
            float area = (U[10] * 64.0f) * 64.0f;
            float ratio = U[11];
            float eh = fminf(fmaxf(sqrtf(area * ratio), 1.0f), 64.0f);
            float ew = fminf(fmaxf(sqrtf(area / ratio), 1.0f), 64.0f);
            float top = U[12] * (64.0f - eh);
            float left = U[13] * (64.0f - ew);
            if (lane == 0) {
                P.m00 = m00; P.m01 = m01; P.m10 = m10; P.m11 = m11;
                P.tx = U[3] * 64.0f;  P.ty = U[4] * 64.0f;
                P.flip = (U[5] < 0.6f);
                P.br = U[6]; P.ct = U[7]; P.st = U[8];
                P.blur = (U[9] < 0.3f);
                P.eapply = (U[14] < 0.3f);
                P.gapply = (U[16] < 0.3f);
                P.kv0 = K[34]; P.kv1 = K[35];
            }
            __syncwarp();
            float c0 = (float)lane, c1 = (float)(lane + 32);
            float gd = U[15], gl = floorf(U[15] * 0.6f);
            uint32_t g0 = __ballot_sync(0xffffffffu, fmodf(c0, gd) < gl);
            uint32_t g1 = __ballot_sync(0xffffffffu, fmodf(c1, gd) < gl);
            uint32_t r0 = __ballot_sync(0xffffffffu, c0 >= top && c0 < top + eh);
            uint32_t r1 = __ballot_sync(0xffffffffu, c1 >= top && c1 < top + eh);
            uint32_t q0 = __ballot_sync(0xffffffffu, c0 >= left && c0 < left + ew);
            uint32_t q1 = __ballot_sync(0xffffffffu, c1 >= left && c1 < left + ew);
            if (lane == 0) {
                gm[0] = g0; gm[1] = g1;
                er_row[0] = r0; er_row[1] = r1;
                er_col[0] = q0; er_col[1] = q1;
            }
        }
    }

    // ================= staging border zero ====================================
    // RG: full rows {0,1,66,67} (34 float4 each = 136) + side cols rows 2..65 (128)
    #pragma unroll
    for (int i = tid; i < 264; i += NT) {
        int addr;
        if (i < 136) {
            int r = i / 34, c4 = i % 34;
            int row = (r < 2) ? r : 64 + r;
            addr = row * RGSTRIDE + c4 * 4;
        } else {
            int j = i - 136;
            int r = 2 + (j >> 1);
            addr = r * RGSTRIDE + ((j & 1) ? 132 : 0);
        }
        *(float4*)(smem + addr) = make_float4(0.f, 0.f, 0.f, 0.f);
    }
    // B: full rows {0,1,66,67} (18 float4 each = 72) + side col blocks (128)
    #pragma unroll
    for (int i = tid; i < 200; i += NT) {
        int addr;
        if (i < 72) {
            int r = i / 18, c4 = i % 18;
            int row = (r < 2) ? r : 64 + r;
            addr = row * BSTRIDE + c4 * 4;
        } else {
            int j = i - 72;
            int r = 2 + (j >> 1);
            addr = r * BSTRIDE + ((j & 1) ? 68 : 0);
        }
        *(float4*)(sBp + addr) = make_float4(0.f, 0.f, 0.f, 0.f);
    }

    // ================= interior load: planar global -> RG + B ================
    {
        const float4* gin4 = (const float4*)(gin + (size_t)b * CHW);
        #pragma unroll
        for (int j = 0; j < 2; j++) {
            int q = tid + j * NT;               // 0..1023 quads (4px)
            float4 R4 = gin4[q];
            float4 G4 = gin4[q + 1024];
            float4 B4 = gin4[q + 2048];
            int h = q >> 4, w = (q & 15) << 2;
            int rgbase = ((h + 2) * 68 + (w + 2)) * 2;
            *(float4*)(sRG + rgbase)     = make_float4(R4.x, G4.x, R4.y, G4.y);
            *(float4*)(sRG + rgbase + 4) = make_float4(R4.z, G4.z, R4.w, G4.w);
            *(float4*)(sBp + (h + 2) * BSTRIDE + (w + 4)) = B4;
        }
    }
    __syncthreads();

    // ================= phase 1: gather into registers + sum ==================
    const float m00 = P.m00, m01 = P.m01, m10 = P.m10, m11 = P.m11;
    const bool flip = P.flip;
    const bool doblur = P.blur;
    const int w = tid & 63;
    const int h0 = tid >> 6;         // 0..7; rows h0 + 8k
    const int wd = flip ? (63 - w) : w;

    float vr[8], vg[8], vb[8];
    {
        const float gx = (float)w - 31.5f;
        float sx = m00 * gx + m01 * ((float)h0 - 31.5f) - P.tx + 31.5f;
        float sy = m10 * gx + m11 * ((float)h0 - 31.5f) - P.ty + 31.5f;
        const float dx8 = 8.0f * m01, dy8 = 8.0f * m11;
        float lsum = 0.f;
        #pragma unroll
        for (int k = 0; k < 8; k++) {
            float x0f = floorf(sx), y0f = floorf(sy);
            float wx = sx - x0f, wy = sy - y0f;
            int xi = min(max((int)x0f, -2), 64);
            int yi = min(max((int)y0f, -2), 64);
            const float* pRG = sRG + ((yi + 2) * 68 + (xi + 2)) * 2;  // even -> 8B aligned
            const float* pB  = sBp + (yi + 2) * BSTRIDE + (xi + 4);
            float2 t00 = *(const float2*)(pRG);
            float2 t01 = *(const float2*)(pRG + 2);
            float2 t10 = *(const float2*)(pRG + RGSTRIDE);
            float2 t11 = *(const float2*)(pRG + RGSTRIDE + 2);
            float b00 = pB[0], b01 = pB[1], b10 = pB[BSTRIDE], b11 = pB[BSTRIDE + 1];
            float w11 = wx * wy;
            float w01 = wx - w11;
            float w10 = wy - w11;
            float w00 = 1.0f - wx - wy + w11;
            vr[k] = t00.x * w00 + t01.x * w01 + t10.x * w10 + t11.x * w11;
            vg[k] = t00.y * w00 + t01.y * w01 + t10.y * w10 + t11.y * w11;
            vb[k] = b00  * w00 + b01  * w01 + b10  * w10 + b11  * w11;
            lsum += vr[k] + vg[k] + vb[k];
            sx += dx8; sy += dy8;
        }
        #pragma unroll
        for (int off = 16; off > 0; off >>= 1)
            lsum += __shfl_xor_sync(0xffffffffu, lsum, off);
        if ((tid & 31) == 0) red[tid >> 5] = lsum;
    }
    __syncthreads();   // red ready; staging now DEAD (all gathers done)

    // ---------------- per-warp mean finish ----------------
    float alpha, beta, delta;
    {
        const int lane = tid & 31;
        float t = (lane < NT / 32) ? red[lane] : 0.f;
        #pragma unroll
        for (int off = 8; off > 0; off >>= 1)
            t += __shfl_xor_sync(0xffffffffu, t, off);
        t = __shfl_sync(0xffffffffu, t, 0);
        float mean = (P.br * t) * (1.0f / 12288.0f);
        float bc = P.br * P.ct;
        alpha = P.st * bc;
        beta  = (1.0f - P.st) * bc;
        delta = mean * (1.0f - P.ct);
    }
    const bool eap = P.eapply, gap = P.gapply;
    const uint32_t kv0 = P.kv0, kv1 = P.kv1;
    float* o = gout + (size_t)b * CHW;
    const bool ecol_hit = eap && ((er_col[wd >> 5] >> (wd & 31)) & 1u);
    const bool gcol_hit = gap && ((gm[wd >> 5] >> (wd & 31)) & 1u);

    if (!doblur) {
        // ========== non-blur: jitter + masks + clamp straight from regs ======
        #pragma unroll
        for (int k = 0; k < 8; k++) {
            const int h = h0 + 8 * k;
            float r = vr[k], g = vg[k], bl = vb[k];
            float gray = 0.299f * r + 0.587f * g + 0.114f * bl;
            float v0 = alpha * r  + beta * gray + delta;
            float v1 = alpha * g  + beta * gray + delta;
            float v2 = alpha * bl + beta * gray + delta;
            if (ecol_hit && ((er_row[h >> 5] >> (h & 31)) & 1u)) {
                uint32_t rbase = ((uint32_t)b * 3u) * 4096u + (uint32_t)(h * 64 + wd);
                v0 = u01f(rb32(kv0, kv1, rbase));
                v1 = u01f(rb32(kv0, kv1, rbase + 4096u));
                v2 = u01f(rb32(kv0, kv1, rbase + 8192u));
            }
            if (gcol_hit && ((gm[h >> 5] >> (h & 31)) & 1u)) {
                v0 = 0.f; v1 = 0.f; v2 = 0.f;
            }
            const int base = h * 64 + wd;
            o[base]            = fminf(fmaxf(v0, 0.f), 1.f);
            o[HWpx + base]     = fminf(fmaxf(v1, 0.f), 1.f);
            o[2 * HWpx + base] = fminf(fmaxf(v2, 0.f), 1.f);
        }
    } else {
        // ========== blur: spill regs -> padded overlay, 9-tap, jitter ========
        // border zero + interior STS write DISJOINT addresses -> one barrier
        #pragma unroll
        for (int i = tid; i < 792; i += NT) {
            int plane = i / 264;
            int r = i - plane * 264;
            int row, col;
            if (r < 136) { row = (r < 68) ? 0 : 65; col = (r < 68) ? r : r - 68; }
            else { int r2 = r - 136; row = 1 + (r2 >> 1); col = (r2 & 1) ? 65 : 0; }
            smem[plane * WPLANE + row * WSTR + col] = 0.f;
        }
        #pragma unroll
        for (int k = 0; k < 8; k++) {
            const int h = h0 + 8 * k;
            const int off = (h + 1) * WSTR + (wd + 1);
            smem[off]              = vr[k];
            smem[WPLANE + off]     = vg[k];
            smem[2 * WPLANE + off] = vb[k];
        }
        __syncthreads();

        const float rx = 1.0f - 0.25f * ((wd == 0) + (wd == 63));
        #pragma unroll
        for (int k = 0; k < 8; k++) {
            const int h = h0 + 8 * k;
            float v[3];
            #pragma unroll
            for (int c = 0; c < 3; c++) {
                const float* p = smem + c * WPLANE + h * WSTR + wd;  // window TL
                float t0 = 0.25f * (p[0] + p[2]) + 0.5f * p[1];
                float t1 = 0.25f * (p[WSTR] + p[WSTR + 2]) + 0.5f * p[WSTR + 1];
                float t2 = 0.25f * (p[2 * WSTR] + p[2 * WSTR + 2]) + 0.5f * p[2 * WSTR + 1];
                v[c] = 0.25f * (t0 + t2) + 0.5f * t1;
            }
            float S = rx * (1.0f - 0.25f * ((h == 0) + (h == 63)));
            float gray = 0.299f * v[0] + 0.587f * v[1] + 0.114f * v[2];
            float dd = delta * S;
            float v0 = alpha * v[0] + beta * gray + dd;
            float v1 = alpha * v[1] + beta * gray + dd;
            float v2 = alpha * v[2] + beta * gray + dd;
            if (ecol_hit && ((er_row[h >> 5] >> (h & 31)) & 1u)) {
                uint32_t rbase = ((uint32_t)b * 3u) * 4096u + (uint32_t)(h * 64 + wd);
                v0 = u01f(rb32(kv0, kv1, rbase));
                v1 = u01f(rb32(kv0, kv1, rbase + 4096u));
                v2 = u01f(rb32(kv0, kv1, rbase + 8192u));
            }
            if (gcol_hit && ((gm[h >> 5] >> (h & 31)) & 1u)) {
                v0 = 0.f; v1 = 0.f; v2 = 0.f;
            }
            const int base = h * 64 + wd;
            o[base]            = fminf(fmaxf(v0, 0.f), 1.f);
            o[HWpx + base]     = fminf(fmaxf(v1, 0.f), 1.f);
            o[2 * HWpx + base] = fminf(fmaxf(v2, 0.f), 1.f);
        }
    }
}

extern "C" void kernel_launch(void* const* d_in, const int* in_sizes, int n_in,
                              void* d_out, int out_size) {
    (void)in_sizes; (void)n_in; (void)out_size;
    const float* x = (const float*)d_in[0];
    float* out = (float*)d_out;
    cudaFuncSetAttribute(aug_kernel, cudaFuncAttributeMaxDynamicSharedMemorySize,
                         STAGE_FLOATS * (int)sizeof(float));
    aug_kernel<<<BATCH, NT, STAGE_FLOATS * sizeof(float)>>>(x, out);
}

// round 9
// speedup vs baseline: 1.7460x; 1.0123x over previous
#include <cuda_runtime.h>
#include <stdint.h>

// ============================================================================
// EnhancedAntiOverfittingAugmentation — round 9: R8 + LDG-first + BB-pair B.
//  - LDG-first: all input loads issued before border-zero + param Threefry,
//    hiding DRAM latency under param computation (and vice versa)
//  - staging: RG interleaved (68x68x2) + BB pair plane (entry x = (B[x],B[x+1]))
//    -> bilinear gather = 4x LDS.64 (RG) + 2x LDS.64 (B) per px, all aligned
//  - register-resident warped image (8px x 3ch per thread @ NT=512)
//  - non-blur CTAs: regs -> jitter/masks -> out; blur CTAs: SMEM overlay 9-tap
// Randomness replicates JAX Threefry-2x32, threefry_partitionable=True.
// 512 thr, 74KB smem, 2 CTAs/SM.
// ============================================================================

#define NT 512
#define BATCH 2048
#define HWpx 4096
#define CHW 12288
#define RGSTRIDE 136              // floats per RG row (68 entries * 2)
#define OFF_BB (68 * 136)         // 9248
#define BBSTRIDE 136              // floats per BB row (68 entries * 2)
#define STAGE_FLOATS (OFF_BB + 68 * BBSTRIDE)   // 18496 floats = 73984 B
// blur overlay planes (1px pad), overlaid on dead staging (13464 <= 18496)
#define WSTR 68
#define WPLANE (66 * 68)          // 4488

__constant__ int   c_parent[16] = {0,0,0,0, 2,2,2, 4,4,4,4,4,4, 5,5, 0};
__constant__ int   c_child[16]  = {0,1,2,3, 0,1,2, 0,1,2,3,4,5, 0,1, 0};
__constant__ int   c_src[17]    = {6,7,8,9,9, 1, 10,11,12, 3, 13,14,15,16, 18, 19, 20};
__constant__ int   c_cnt[17]    = {0,0,0,1,2, 0, 0,0,0, 0, 0,0,0,0, 0, 0, 0};
__constant__ float c_lo[17]  = {-25.f,-15.f,0.85f,-0.15f,-0.15f, 0.f, 0.7f,0.7f,0.8f,
                                0.f, 0.02f,0.3f,0.f,0.f, 0.f, 8.f, 0.f};
__constant__ float c_hi[17]  = {25.f,15.f,1.15f,0.15f,0.15f, 1.f, 1.3f,1.3f,1.2f,
                                1.f, 0.1f,3.0f,1.f,1.f, 1.f, 32.f, 1.f};
#define DEGf 0.017453292519943295f
__constant__ float c_mul[17] = {DEGf,DEGf,1.f,1.f,1.f, 1.f, 1.f,1.f,1.f,
                                1.f, 1.f,1.f,1.f,1.f, 1.f, 1.f, 1.f};

__device__ __forceinline__ uint32_t rotl32(uint32_t v, int d) {
    return (v << d) | (v >> (32 - d));
}

// Threefry-2x32, 20 rounds, exactly as in jax._src.prng
__device__ __forceinline__ void tf2x32(uint32_t k0, uint32_t k1,
                                       uint32_t x0, uint32_t x1,
                                       uint32_t &o0, uint32_t &o1) {
    const uint32_t ks2 = k0 ^ k1 ^ 0x1BD11BDAu;
    x0 += k0; x1 += k1;
#define TFR(r) { x0 += x1; x1 = rotl32(x1, (r)); x1 ^= x0; }
    TFR(13) TFR(15) TFR(26) TFR(6)   x0 += k1;  x1 += ks2 + 1u;
    TFR(17) TFR(29) TFR(16) TFR(24)  x0 += ks2; x1 += k0 + 2u;
    TFR(13) TFR(15) TFR(26) TFR(6)   x0 += k0;  x1 += k1 + 3u;
    TFR(17) TFR(29) TFR(16) TFR(24)  x0 += k1;  x1 += ks2 + 4u;
    TFR(13) TFR(15) TFR(26) TFR(6)   x0 += ks2; x1 += k0 + 5u;
#undef TFR
    o0 = x0; o1 = x1;
}

__device__ __forceinline__ uint32_t rb32(uint32_t k0, uint32_t k1, uint32_t idx) {
    uint32_t a, b; tf2x32(k0, k1, 0u, idx, a, b); return a ^ b;
}

__device__ __forceinline__ float u01f(uint32_t bits) {
    return __uint_as_float((bits >> 9) | 0x3f800000u) - 1.0f;
}
__device__ __forceinline__ float unif(uint32_t bits, float lo, float hi) {
    return fmaxf(lo, u01f(bits) * (hi - lo) + lo);
}

struct SampleParams {
    float m00, m01, m10, m11, tx, ty;
    float br, ct, st;
    uint32_t kv0, kv1;
    int flip, blur, eapply, gapply;
};

__global__ void __launch_bounds__(NT, 2)
aug_kernel(const float* __restrict__ gin, float* __restrict__ gout) {
    extern __shared__ float smem[];
    float* sRG = smem;             // 68x68 entries x float2 (R,G), pad 2
    float* sBB = smem + OFF_BB;    // 68x68 entries x float2 (B[x],B[x+1]), pad 2
    __shared__ SampleParams P;
    __shared__ float red[NT / 32];
    __shared__ uint32_t K[42];
    __shared__ float U[17];
    __shared__ uint32_t gm[2], er_row[2], er_col[2];

    const int b = blockIdx.x;
    const int tid = threadIdx.x;

    // ================= LDG-FIRST: issue all input loads ======================
    float4 Rv[2], Gv[2], Bv[2];
    float Bn[2];
    {
        const float4* gin4 = (const float4*)(gin + (size_t)b * CHW);
        #pragma unroll
        for (int j = 0; j < 2; j++) {
            int q = tid + j * NT;               // 0..1023 quads (4px)
            Rv[j] = gin4[q];
            Gv[j] = gin4[q + 1024];
            Bv[j] = gin4[q + 2048];
        }
        const float* ginB = gin + (size_t)b * CHW + 2 * HWpx;
        #pragma unroll
        for (int j = 0; j < 2; j++) {
            int q = tid + j * NT;
            int h = q >> 4, wn = ((q & 15) << 2) + 4;
            Bn[j] = (wn < 64) ? ginB[h * 64 + wn] : 0.f;
        }
    }

    // ================= staging border zero (under LDG shadow) ================
    // [0,264): RG full rows + side col4s; [264,464): BB full rows + right col4;
    // [464,528): BB left col0 float2
    #pragma unroll
    for (int i = tid; i < 528; i += NT) {
        if (i < 264) {
            int addr;
            if (i < 136) {
                int r = i / 34, c4 = i % 34;
                int row = (r < 2) ? r : 64 + r;
                addr = row * RGSTRIDE + c4 * 4;
            } else {
                int j = i - 136;
                int r = 2 + (j >> 1);
                addr = r * RGSTRIDE + ((j & 1) ? 132 : 0);
            }
            *(float4*)(sRG + addr) = make_float4(0.f, 0.f, 0.f, 0.f);
        } else if (i < 464) {
            int k = i - 264;
            int addr;
            if (k < 136) {
                int r = k / 34, c4 = k % 34;
                int row = (r < 2) ? r : 64 + r;
                addr = row * BBSTRIDE + c4 * 4;
            } else {
                int r = 2 + (k - 136);          // rows 2..65, right cols 66,67
                addr = r * BBSTRIDE + 132;
            }
            *(float4*)(sBB + addr) = make_float4(0.f, 0.f, 0.f, 0.f);
        } else {
            int r = 2 + (i - 464);              // rows 2..65, left col 0
            *(float2*)(sBB + r * BBSTRIDE) = make_float2(0.f, 0.f);
        }
    }

    // ================= params, uniform control flow (warp 0) =================
    // runs while this warp's (and others') LDGs are in flight
    if (tid < 32) {
        const int lane = tid;
        const uint32_t ub = (uint32_t)b;
        uint32_t o0, o1;
        tf2x32(0u, 42u, 0u, (uint32_t)min(lane, 5), o0, o1);
        if (lane < 6) { K[2 * lane] = o0; K[2 * lane + 1] = o1; }
        __syncwarp();
        {
            int li = min(lane, 15);
            int p = c_parent[li];
            tf2x32(K[2 * p], K[2 * p + 1], 0u, (uint32_t)c_child[li], o0, o1);
            if (lane < 15) { K[12 + 2 * lane] = o0; K[13 + 2 * lane] = o1; }
        }
        __syncwarp();
        {
            int li = min(lane, 16);
            int s = c_src[li];
            int cs = c_cnt[li];
            uint32_t cnt = (cs == 0) ? ub : ((cs == 1) ? 2u * ub : 2u * ub + 1u);
            uint32_t bits = rb32(K[2 * s], K[2 * s + 1], cnt);
            float u = unif(bits, c_lo[li], c_hi[li]) * c_mul[li];
            if (lane == 15) u = floorf(u);
            if (lane < 17) U[lane] = u;
        }
        __syncwarp();
        {
            float ang = U[0], shr = U[1], scl = U[2];
            float cc = cosf(ang), ss = sinf(ang), t = tanf(shr);
            float m00 = (cc - t * (-ss)) / scl;
            float m01 = (ss - t * cc) / scl;
            float m10 = (-ss) / scl;
            float m11 = cc / scl;
            float area = (U[10] * 64.0f) * 64.0f;
            float ratio = U[11];
            float eh = fminf(fmaxf(sqrtf(area * ratio), 1.0f), 64.0f);
            float ew = fminf(fmaxf(sqrtf(area / ratio), 1.0f), 64.0f);
            float top = U[12] * (64.0f - eh);
            float left = U[13] * (64.0f - ew);
            if (lane == 0) {
                P.m00 = m00; P.m01 = m01; P.m10 = m10; P.m11 = m11;
                P.tx = U[3] * 64.0f;  P.ty = U[4] * 64.0f;
                P.flip = (U[5] < 0.6f);
                P.br = U[6]; P.ct = U[7]; P.st = U[8];
                P.blur = (U[9] < 0.3f);
                P.eapply = (U[14] < 0.3f);
                P.gapply = (U[16] < 0.3f);
                P.kv0 = K[34]; P.kv1 = K[35];
            }
            __syncwarp();
            float c0 = (float)lane, c1 = (float)(lane + 32);
            float gd = U[15], gl = floorf(U[15] * 0.6f);
            uint32_t g0 = __ballot_sync(0xffffffffu, fmodf(c0, gd) < gl);
            uint32_t g1 = __ballot_sync(0xffffffffu, fmodf(c1, gd) < gl);
            uint32_t r0 = __ballot_sync(0xffffffffu, c0 >= top && c0 < top + eh);
            uint32_t r1 = __ballot_sync(0xffffffffu, c1 >= top && c1 < top + eh);
            uint32_t q0 = __ballot_sync(0xffffffffu, c0 >= left && c0 < left + ew);
            uint32_t q1 = __ballot_sync(0xffffffffu, c1 >= left && c1 < left + ew);
            if (lane == 0) {
                gm[0] = g0; gm[1] = g1;
                er_row[0] = r0; er_row[1] = r1;
                er_col[0] = q0; er_col[1] = q1;
            }
        }
    }

    // ================= interior STS: RG entries + BB pair entries ============
    #pragma unroll
    for (int j = 0; j < 2; j++) {
        int q = tid + j * NT;
        int h = q >> 4, wq = (q & 15) << 2;
        int rgbase = ((h + 2) * 68 + (wq + 2)) * 2;
        float4 R4 = Rv[j], G4 = Gv[j], B4 = Bv[j];
        *(float4*)(sRG + rgbase)     = make_float4(R4.x, G4.x, R4.y, G4.y);
        *(float4*)(sRG + rgbase + 4) = make_float4(R4.z, G4.z, R4.w, G4.w);
        float* bb = sBB + ((h + 2) * 68 + (wq + 2)) * 2;
        *(float2*)(bb)     = make_float2(B4.x, B4.y);
        *(float2*)(bb + 2) = make_float2(B4.y, B4.z);
        *(float2*)(bb + 4) = make_float2(B4.z, B4.w);
        *(float2*)(bb + 6) = make_float2(B4.w, Bn[j]);
        if (wq == 0)  // left edge pair: (B[-1], B[0]) = (0, B4.x)
            *(float2*)(sBB + ((h + 2) * 68 + 1) * 2) = make_float2(0.f, B4.x);
    }
    __syncthreads();

    // ================= phase 1: gather into registers + sum ==================
    const float m00 = P.m00, m01 = P.m01, m10 = P.m10, m11 = P.m11;
    const bool flip = P.flip;
    const bool doblur = P.blur;
    const int w = tid & 63;
    const int h0 = tid >> 6;         // 0..7; rows h0 + 8k
    const int wd = flip ? (63 - w) : w;

    float vr[8], vg[8], vb[8];
    {
        const float gx = (float)w - 31.5f;
        float sx = m00 * gx + m01 * ((float)h0 - 31.5f) - P.tx + 31.5f;
        float sy = m10 * gx + m11 * ((float)h0 - 31.5f) - P.ty + 31.5f;
        const float dx8 = 8.0f * m01, dy8 = 8.0f * m11;
        float lsum = 0.f;
        #pragma unroll
        for (int k = 0; k < 8; k++) {
            float x0f = floorf(sx), y0f = floorf(sy);
            float wx = sx - x0f, wy = sy - y0f;
            int xi = min(max((int)x0f, -2), 64);
            int yi = min(max((int)y0f, -2), 64);
            const int ebase = ((yi + 2) * 68 + (xi + 2)) * 2;   // even -> 8B aligned
            const float* pRG = sRG + ebase;
            const float* pBB = sBB + ebase;
            float2 t00 = *(const float2*)(pRG);
            float2 t01 = *(const float2*)(pRG + 2);
            float2 t10 = *(const float2*)(pRG + RGSTRIDE);
            float2 t11 = *(const float2*)(pRG + RGSTRIDE + 2);
            float2 bb0 = *(const float2*)(pBB);
            float2 bb1 = *(const float2*)(pBB + BBSTRIDE);
            float w11 = wx * wy;
            float w01 = wx - w11;
            float w10 = wy - w11;
            float w00 = 1.0f - wx - wy + w11;
            vr[k] = t00.x * w00 + t01.x * w01 + t10.x * w10 + t11.x * w11;
            vg[k] = t00.y * w00 + t01.y * w01 + t10.y * w10 + t11.y * w11;
            vb[k] = bb0.x * w00 + bb0.y * w01 + bb1.x * w10 + bb1.y * w11;
            lsum += vr[k] + vg[k] + vb[k];
            sx += dx8; sy += dy8;
        }
        #pragma unroll
        for (int off = 16; off > 0; off >>= 1)
            lsum += __shfl_xor_sync(0xffffffffu, lsum, off);
        if ((tid & 31) == 0) red[tid >> 5] = lsum;
    }
    __syncthreads();   // red ready; staging now DEAD (all gathers done)

    // ---------------- per-warp mean finish ----------------
    float alpha, beta, delta;
    {
        const int lane = tid & 31;
        float t = (lane < NT / 32) ? red[lane] : 0.f;
        #pragma unroll
        for (int off = 8; off > 0; off >>= 1)
            t += __shfl_xor_sync(0xffffffffu, t, off);
        t = __shfl_sync(0xffffffffu, t, 0);
        float mean = (P.br * t) * (1.0f / 12288.0f);
        float bc = P.br * P.ct;
        alpha = P.st * bc;
        beta  = (1.0f - P.st) * bc;
        delta = mean * (1.0f - P.ct);
    }
    const bool eap = P.eapply, gap = P.gapply;
    const uint32_t kv0 = P.kv0, kv1 = P.kv1;
    float* o = gout + (size_t)b * CHW;
    const bool ecol_hit = eap && ((er_col[wd >> 5] >> (wd & 31)) & 1u);
    const bool gcol_hit = gap && ((gm[wd >> 5] >> (wd & 31)) & 1u);

    if (!doblur) {
        // ========== non-blur: jitter + masks + clamp straight from regs ======
        #pragma unroll
        for (int k = 0; k < 8; k++) {
            const int h = h0 + 8 * k;
            float r = vr[k], g = vg[k], bl = vb[k];
            float gray = 0.299f * r + 0.587f * g + 0.114f * bl;
            float v0 = alpha * r  + beta * gray + delta;
            float v1 = alpha * g  + beta * gray + delta;
            float v2 = alpha * bl + beta * gray + delta;
            if (ecol_hit && ((er_row[h >> 5] >> (h & 31)) & 1u)) {
                uint32_t rbase = ((uint32_t)b * 3u) * 4096u + (uint32_t)(h * 64 + wd);
                v0 = u01f(rb32(kv0, kv1, rbase));
                v1 = u01f(rb32(kv0, kv1, rbase + 4096u));
                v2 = u01f(rb32(kv0, kv1, rbase + 8192u));
            }
            if (gcol_hit && ((gm[h >> 5] >> (h & 31)) & 1u)) {
                v0 = 0.f; v1 = 0.f; v2 = 0.f;
            }
            const int base = h * 64 + wd;
            o[base]            = fminf(fmaxf(v0, 0.f), 1.f);
            o[HWpx + base]     = fminf(fmaxf(v1, 0.f), 1.f);
            o[2 * HWpx + base] = fminf(fmaxf(v2, 0.f), 1.f);
        }
    } else {
        // ========== blur: spill regs -> padded overlay, 9-tap, jitter ========
        #pragma unroll
        for (int i = tid; i < 792; i += NT) {
            int plane = i / 264;
            int r = i - plane * 264;
            int row, col;
            if (r < 136) { row = (r < 68) ? 0 : 65; col = (r < 68) ? r : r - 68; }
            else { int r2 = r - 136; row = 1 + (r2 >> 1); col = (r2 & 1) ? 65 : 0; }
            smem[plane * WPLANE + row * WSTR + col] = 0.f;
        }
        #pragma unroll
        for (int k = 0; k < 8; k++) {
            const int h = h0 + 8 * k;
            const int off = (h + 1) * WSTR + (wd + 1);
            smem[off]              = vr[k];
            smem[WPLANE + off]     = vg[k];
            smem[2 * WPLANE + off] = vb[k];
        }
        __syncthreads();

        const float rx = 1.0f - 0.25f * ((wd == 0) + (wd == 63));
        #pragma unroll
        for (int k = 0; k < 8; k++) {
            const int h = h0 + 8 * k;
            float v[3];
            #pragma unroll
            for (int c = 0; c < 3; c++) {
                const float* p = smem + c * WPLANE + h * WSTR + wd;  // window TL
                float t0 = 0.25f * (p[0] + p[2]) + 0.5f * p[1];
                float t1 = 0.25f * (p[WSTR] + p[WSTR + 2]) + 0.5f * p[WSTR + 1];
                float t2 = 0.25f * (p[2 * WSTR] + p[2 * WSTR + 2]) + 0.5f * p[2 * WSTR + 1];
                v[c] = 0.25f * (t0 + t2) + 0.5f * t1;
            }
            float S = rx * (1.0f - 0.25f * ((h == 0) + (h == 63)));
            float gray = 0.299f * v[0] + 0.587f * v[1] + 0.114f * v[2];
            float dd = delta * S;
            float v0 = alpha * v[0] + beta * gray + dd;
            float v1 = alpha * v[1] + beta * gray + dd;
            float v2 = alpha * v[2] + beta * gray + dd;
            if (ecol_hit && ((er_row[h >> 5] >> (h & 31)) & 1u)) {
                uint32_t rbase = ((uint32_t)b * 3u) * 4096u + (uint32_t)(h * 64 + wd);
                v0 = u01f(rb32(kv0, kv1, rbase));
                v1 = u01f(rb32(kv0, kv1, rbase + 4096u));
                v2 = u01f(rb32(kv0, kv1, rbase + 8192u));
            }
            if (gcol_hit && ((gm[h >> 5] >> (h & 31)) & 1u)) {
                v0 = 0.f; v1 = 0.f; v2 = 0.f;
            }
            const int base = h * 64 + wd;
            o[base]            = fminf(fmaxf(v0, 0.f), 1.f);
            o[HWpx + base]     = fminf(fmaxf(v1, 0.f), 1.f);
            o[2 * HWpx + base] = fminf(fmaxf(v2, 0.f), 1.f);
        }
    }
}

extern "C" void kernel_launch(void* const* d_in, const int* in_sizes, int n_in,
                              void* d_out, int out_size) {
    (void)in_sizes; (void)n_in; (void)out_size;
    const float* x = (const float*)d_in[0];
    float* out = (float*)d_out;
    cudaFuncSetAttribute(aug_kernel, cudaFuncAttributeMaxDynamicSharedMemorySize,
                         STAGE_FLOATS * (int)sizeof(float));
    aug_kernel<<<BATCH, NT, STAGE_FLOATS * sizeof(float)>>>(x, out);
}